// round 1
// baseline (speedup 1.0000x reference)
#include <cuda_runtime.h>
#include <math.h>

// Problem constants
#define BB 2
#define NN 2048
#define EE 1024
#define HH 8
#define DD 64          // half-head dim
#define D2 128         // 2*D, v head dim
#define H2 16          // 2*H
#define MROWS 4096     // B*N

// ---------------- scratch (device globals; no allocation allowed) ------------
__device__ float g_q  [(size_t)BB * H2 * NN * DD];       // [b,h2,n,d] (scaled)
__device__ float g_kT [(size_t)BB * H2 * DD * NN];       // [b,h2,d,n]
__device__ float g_v  [(size_t)BB * HH * NN * D2];       // [b,h,n,c]
__device__ float g_s  [(size_t)BB * H2 * NN * NN];       // raw scores  (537 MB)
__device__ float g_w  [(size_t)BB * HH * NN * NN];       // combined weights (268 MB)
__device__ float g_po [(size_t)BB * HH * NN * D2];       // pre-LN o
__device__ float g_oln[(size_t)MROWS * EE];              // post-LN, [b,n, h*128+c]
__device__ float g_lam;

// ---------------- lambda ------------------------------------------------------
__global__ void lam_kernel(const float* __restrict__ lq1, const float* __restrict__ lk1,
                           const float* __restrict__ lq2, const float* __restrict__ lk2)
{
    int t = threadIdx.x;            // 64 threads
    float p1 = lq1[t] * lk1[t];
    float p2 = lq2[t] * lk2[t];
    for (int o = 16; o > 0; o >>= 1) {
        p1 += __shfl_xor_sync(0xffffffffu, p1, o);
        p2 += __shfl_xor_sync(0xffffffffu, p2, o);
    }
    __shared__ float sh[4];
    if ((t & 31) == 0) { sh[(t >> 5) * 2] = p1; sh[(t >> 5) * 2 + 1] = p2; }
    __syncthreads();
    if (t == 0) {
        float S1 = sh[0] + sh[2];
        float S2 = sh[1] + sh[3];
        float lam_init = 0.8f - 0.6f * expf(-0.3f * 12.0f);
        g_lam = expf(S1) - expf(S2) + lam_init;
    }
}

// ---------------- generic tiled SGEMM (128x128x8, 8x8 micro) -----------------
#define TBM 128
#define TBN 128
#define TBK 8

#define MODE_Q     0
#define MODE_K     1
#define MODE_V     2
#define MODE_S     3
#define MODE_O     4
#define MODE_FINAL 5

template <int MODE>
__global__ __launch_bounds__(256)
void sgemm_kernel(const float* __restrict__ A, const float* __restrict__ Bm,
                  float* __restrict__ C,
                  int M, int Ncols, int Kd,
                  long aBatchStride, long bBatchStride)
{
    __shared__ float As[TBK][TBM];
    __shared__ float Bs[TBK][TBN];

    const int z = blockIdx.z;
    const float* Ab = A + (long)z * aBatchStride;
    const float* Bb = Bm + (long)z * bBatchStride;

    const int bm0 = blockIdx.y * TBM;
    const int bn0 = blockIdx.x * TBN;
    const int tid = threadIdx.x;
    const int tx = tid & 15;
    const int ty = tid >> 4;

    const int arow = tid >> 1;
    const int acol = (tid & 1) * 4;
    const int brow = tid >> 5;
    const int bcol = (tid & 31) * 4;

    float acc[8][8];
#pragma unroll
    for (int i = 0; i < 8; i++)
#pragma unroll
        for (int j = 0; j < 8; j++) acc[i][j] = 0.0f;

    for (int k0 = 0; k0 < Kd; k0 += TBK) {
        float4 av = *(const float4*)&Ab[(long)(bm0 + arow) * Kd + k0 + acol];
        As[acol + 0][arow] = av.x;
        As[acol + 1][arow] = av.y;
        As[acol + 2][arow] = av.z;
        As[acol + 3][arow] = av.w;
        float4 bv = *(const float4*)&Bb[(long)(k0 + brow) * Ncols + bn0 + bcol];
        *(float4*)&Bs[brow][bcol] = bv;
        __syncthreads();
#pragma unroll
        for (int kk = 0; kk < TBK; kk++) {
            float a[8], b[8];
            *(float4*)&a[0] = *(float4*)&As[kk][ty * 8];
            *(float4*)&a[4] = *(float4*)&As[kk][ty * 8 + 4];
            *(float4*)&b[0] = *(float4*)&Bs[kk][tx * 8];
            *(float4*)&b[4] = *(float4*)&Bs[kk][tx * 8 + 4];
#pragma unroll
            for (int i = 0; i < 8; i++)
#pragma unroll
                for (int j = 0; j < 8; j++)
                    acc[i][j] += a[i] * b[j];
        }
        __syncthreads();
    }

#pragma unroll
    for (int i = 0; i < 8; i++) {
        int m = bm0 + ty * 8 + i;
#pragma unroll
        for (int j = 0; j < 8; j++) {
            int ch = bn0 + tx * 8 + j;
            float val = acc[i][j];
            if (MODE == MODE_Q) {
                int b_ = m >> 11, n = m & 2047;
                int h2 = ch >> 6, d = ch & 63;
                g_q[(((size_t)(b_ * H2 + h2) * NN) + n) * DD + d] = val * 0.125f;
            } else if (MODE == MODE_K) {
                int b_ = m >> 11, n = m & 2047;
                int h2 = ch >> 6, d = ch & 63;
                g_kT[(((size_t)(b_ * H2 + h2) * DD) + d) * NN + n] = val;
            } else if (MODE == MODE_V) {
                int b_ = m >> 11, n = m & 2047;
                int h = ch >> 7, c = ch & 127;
                g_v[(((size_t)(b_ * HH + h) * NN) + n) * D2 + c] = val;
            } else if (MODE == MODE_S) {
                g_s[(size_t)z * NN * NN + (size_t)m * NN + ch] = val;
            } else if (MODE == MODE_O) {
                g_po[(size_t)z * NN * D2 + (size_t)m * D2 + ch] = val;
            } else {  // MODE_FINAL
                C[(size_t)m * Ncols + ch] = val;
            }
        }
    }
}

// ---------------- softmax + differential combine -----------------------------
__global__ __launch_bounds__(256)
void softmax_combine_kernel()
{
    __shared__ float r1[NN];
    __shared__ float r2[NN];
    __shared__ float redm1[8], redm2[8], reds1[8], reds2[8];

    const int z = blockIdx.x;          // bh*2048 + i
    const int bh = z >> 11;            // 0..15  (b*H + h)
    const int i = z & 2047;
    const int b_ = bh >> 3;
    const int h = bh & 7;

    const size_t base1 = ((size_t)(b_ * H2 + 2 * h) * NN + i) * NN;
    const size_t base2 = ((size_t)(b_ * H2 + 2 * h + 1) * NN + i) * NN;

    const int tid = threadIdx.x;
    const int lane = tid & 31, wid = tid >> 5;

    float m1 = -INFINITY, m2 = -INFINITY;
    for (int j = tid; j < NN; j += 256) {
        float v1 = g_s[base1 + j];
        float v2 = g_s[base2 + j];
        r1[j] = v1; r2[j] = v2;
        m1 = fmaxf(m1, v1);
        m2 = fmaxf(m2, v2);
    }
    for (int o = 16; o > 0; o >>= 1) {
        m1 = fmaxf(m1, __shfl_xor_sync(0xffffffffu, m1, o));
        m2 = fmaxf(m2, __shfl_xor_sync(0xffffffffu, m2, o));
    }
    if (lane == 0) { redm1[wid] = m1; redm2[wid] = m2; }
    __syncthreads();
    float M1 = redm1[0], M2 = redm2[0];
#pragma unroll
    for (int w = 1; w < 8; w++) {
        M1 = fmaxf(M1, redm1[w]);
        M2 = fmaxf(M2, redm2[w]);
    }

    float s1 = 0.0f, s2 = 0.0f;
    for (int j = tid; j < NN; j += 256) {
        float e1 = expf(r1[j] - M1);
        float e2 = expf(r2[j] - M2);
        r1[j] = e1; r2[j] = e2;
        s1 += e1; s2 += e2;
    }
    for (int o = 16; o > 0; o >>= 1) {
        s1 += __shfl_xor_sync(0xffffffffu, s1, o);
        s2 += __shfl_xor_sync(0xffffffffu, s2, o);
    }
    if (lane == 0) { reds1[wid] = s1; reds2[wid] = s2; }
    __syncthreads();
    float S1 = 0.0f, S2 = 0.0f;
#pragma unroll
    for (int w = 0; w < 8; w++) { S1 += reds1[w]; S2 += reds2[w]; }

    const float inv1 = 1.0f / S1;
    const float linv2 = g_lam / S2;
    const size_t wbase = ((size_t)bh * NN + i) * NN;
    for (int j = tid; j < NN; j += 256) {
        g_w[wbase + j] = r1[j] * inv1 - r2[j] * linv2;
    }
}

// ---------------- per-head LayerNorm ------------------------------------------
__global__ __launch_bounds__(128)
void ln_kernel(const float* __restrict__ ln_g, const float* __restrict__ ln_b)
{
    __shared__ float sh1[4], sh2[4];
    const int z = blockIdx.x;          // bh*2048 + n
    const int bh = z >> 11;
    const int n = z & 2047;
    const int b_ = bh >> 3;
    const int h = bh & 7;
    const int tid = threadIdx.x;
    const int lane = tid & 31, wid = tid >> 5;

    float o = g_po[(size_t)z * D2 + tid];

    float s = o;
    for (int off = 16; off > 0; off >>= 1) s += __shfl_xor_sync(0xffffffffu, s, off);
    if (lane == 0) sh1[wid] = s;
    __syncthreads();
    float mu = (sh1[0] + sh1[1] + sh1[2] + sh1[3]) * (1.0f / 128.0f);

    float d = o - mu;
    float sq = d * d;
    for (int off = 16; off > 0; off >>= 1) sq += __shfl_xor_sync(0xffffffffu, sq, off);
    if (lane == 0) sh2[wid] = sq;
    __syncthreads();
    float var = (sh2[0] + sh2[1] + sh2[2] + sh2[3]) * (1.0f / 128.0f);

    float y = d * rsqrtf(var + 1e-5f) * ln_g[tid] + ln_b[tid];
    g_oln[((size_t)(b_ * NN + n)) * EE + h * D2 + tid] = y;
}

// ---------------- launch ------------------------------------------------------
extern "C" void kernel_launch(void* const* d_in, const int* in_sizes, int n_in,
                              void* d_out, int out_size)
{
    const float* x   = (const float*)d_in[0];
    const float* Wq  = (const float*)d_in[1];
    const float* Wk  = (const float*)d_in[2];
    const float* Wv  = (const float*)d_in[3];
    const float* Wo  = (const float*)d_in[4];
    const float* lq1 = (const float*)d_in[5];
    const float* lk1 = (const float*)d_in[6];
    const float* lq2 = (const float*)d_in[7];
    const float* lk2 = (const float*)d_in[8];
    const float* lng = (const float*)d_in[9];
    const float* lnb = (const float*)d_in[10];
    float* out = (float*)d_out;

    float *p_q, *p_kT, *p_v, *p_s, *p_w, *p_oln;
    cudaGetSymbolAddress((void**)&p_q,   g_q);
    cudaGetSymbolAddress((void**)&p_kT,  g_kT);
    cudaGetSymbolAddress((void**)&p_v,   g_v);
    cudaGetSymbolAddress((void**)&p_s,   g_s);
    cudaGetSymbolAddress((void**)&p_w,   g_w);
    cudaGetSymbolAddress((void**)&p_oln, g_oln);

    lam_kernel<<<1, 64>>>(lq1, lk1, lq2, lk2);

    dim3 blk(256);
    // projections: [4096,1024] @ [1024,1024]
    sgemm_kernel<MODE_Q><<<dim3(EE / TBN, MROWS / TBM, 1), blk>>>(x, Wq, nullptr, MROWS, EE, EE, 0, 0);
    sgemm_kernel<MODE_K><<<dim3(EE / TBN, MROWS / TBM, 1), blk>>>(x, Wk, nullptr, MROWS, EE, EE, 0, 0);
    sgemm_kernel<MODE_V><<<dim3(EE / TBN, MROWS / TBM, 1), blk>>>(x, Wv, nullptr, MROWS, EE, EE, 0, 0);

    // scores: batched over 32 half-heads: [2048,64] @ [64,2048]
    sgemm_kernel<MODE_S><<<dim3(NN / TBN, NN / TBM, BB * H2), blk>>>(
        p_q, p_kT, nullptr, NN, NN, DD, (long)NN * DD, (long)DD * NN);

    // softmax + differential combine
    softmax_combine_kernel<<<BB * HH * NN, 256>>>();

    // o = w @ v : batched over 16 heads: [2048,2048] @ [2048,128]
    sgemm_kernel<MODE_O><<<dim3(1, NN / TBM, BB * HH), blk>>>(
        p_w, p_v, nullptr, NN, D2, NN, (long)NN * NN, (long)NN * D2);

    // per-head layernorm
    ln_kernel<<<BB * HH * NN, 128>>>(lng, lnb);

    // final projection: [4096,1024] @ [1024,1024] -> out
    sgemm_kernel<MODE_FINAL><<<dim3(EE / TBN, MROWS / TBM, 1), blk>>>(
        p_oln, Wo, out, MROWS, EE, EE, 0, 0);
}

// round 6
// speedup vs baseline: 2.1709x; 2.1709x over previous
#include <cuda_runtime.h>
#include <cuda_bf16.h>
#include <stdint.h>
#include <math.h>

// Problem constants
#define BB 2
#define NN 2048
#define EE 1024
#define HH 8
#define DD 64          // half-head dim
#define D2 128         // 2*D
#define H2 16          // 2*H
#define MROWS 4096     // B*N

// ---------------- scratch (device globals) -----------------------------------
__device__ float g_q  [(size_t)BB * H2 * NN * DD];   // [b,h2,n,d] scaled
__device__ float g_k  [(size_t)BB * H2 * NN * DD];   // [b,h2,n,d]
__device__ float g_vT [(size_t)BB * HH * D2 * NN];   // [b,h,c,n]  (transposed)
__device__ float g_s  [(size_t)BB * H2 * NN * NN];   // raw scores
__device__ float g_w  [(size_t)BB * HH * NN * NN];   // combined weights
__device__ float g_po [(size_t)BB * HH * NN * D2];   // pre-LN o
__device__ float g_oln[(size_t)MROWS * EE];          // post-LN
__device__ float g_lam;

// ---------------- helpers -----------------------------------------------------
__device__ __forceinline__ uint32_t smem_u32(const void* p) {
    return (uint32_t)__cvta_generic_to_shared(p);
}

#define LDMX4(r0, r1, r2, r3, addr)                                            \
    asm volatile("ldmatrix.sync.aligned.m8n8.x4.shared.b16 {%0,%1,%2,%3}, [%4];" \
                 : "=r"(r0), "=r"(r1), "=r"(r2), "=r"(r3) : "r"(addr))

#define MMA16816(c, a, b)                                                      \
    asm volatile(                                                              \
        "mma.sync.aligned.m16n8k16.row.col.f32.bf16.bf16.f32 "                 \
        "{%0,%1,%2,%3}, {%4,%5,%6,%7}, {%8,%9}, {%0,%1,%2,%3};"                \
        : "+f"((c)[0]), "+f"((c)[1]), "+f"((c)[2]), "+f"((c)[3])               \
        : "r"((a)[0]), "r"((a)[1]), "r"((a)[2]), "r"((a)[3]),                  \
          "r"((b)[0]), "r"((b)[1]))

// hi/lo split of 4 fp32 into two bf16x4 smem tiles (padded pitch, no swizzle)
#define PITCH 72   // bf16 elements per row (144 B -> conflict-free ldmatrix)

__device__ __forceinline__ void split_store(__nv_bfloat162* hb, __nv_bfloat162* lb,
                                            int r, int g, float4 v) {
    __nv_bfloat162 h0, h1, l0, l1;
    h0.x = __float2bfloat16_rn(v.x);
    h0.y = __float2bfloat16_rn(v.y);
    h1.x = __float2bfloat16_rn(v.z);
    h1.y = __float2bfloat16_rn(v.w);
    l0.x = __float2bfloat16_rn(v.x - __bfloat162float(h0.x));
    l0.y = __float2bfloat16_rn(v.y - __bfloat162float(h0.y));
    l1.x = __float2bfloat16_rn(v.z - __bfloat162float(h1.x));
    l1.y = __float2bfloat16_rn(v.w - __bfloat162float(h1.y));
    int idx = (r * PITCH + g * 4) >> 1;
    hb[idx] = h0; hb[idx + 1] = h1;
    lb[idx] = l0; lb[idx + 1] = l1;
}

// ---------------- bf16x3 mma.sync GEMM (128x128 tile, K-chunk 64) ------------
#define MODE_Q     0
#define MODE_K     1
#define MODE_V     2
#define MODE_S     3
#define MODE_O     4
#define MODE_FINAL 5

#define TILE_BYTES (128 * PITCH * 2)              // 18432
static constexpr int SMEM_DYN = 1024 + 4 * TILE_BYTES;

template <int MODE>
__global__ __launch_bounds__(256)
void tgemm(const float* __restrict__ A, const float* __restrict__ Bm,
           float* __restrict__ C, int Kd)
{
    extern __shared__ char dsm[];
    char* base = (char*)(((uintptr_t)dsm + 1023) & ~(uintptr_t)1023);
    __nv_bfloat162* aHi = (__nv_bfloat162*)(base);
    __nv_bfloat162* aLo = (__nv_bfloat162*)(base + TILE_BYTES);
    __nv_bfloat162* bHi = (__nv_bfloat162*)(base + 2 * TILE_BYTES);
    __nv_bfloat162* bLo = (__nv_bfloat162*)(base + 3 * TILE_BYTES);

    const int tid  = threadIdx.x;
    const int z    = blockIdx.z;
    const int bm0  = blockIdx.y * 128;
    const int bn0  = blockIdx.x * 128;
    const int wid  = tid >> 5, lane = tid & 31;
    const int wm   = wid >> 2, wn = wid & 3;   // warp tile: rows wm*64, cols wn*32
    const int tgrp = lane >> 2, tig = lane & 3;

    // operand bases / strides (all K-contiguous)
    const float* Ab;
    int aStride;
    if (MODE == MODE_S)      { Ab = A + (size_t)z * NN * DD; aStride = DD; }
    else if (MODE == MODE_O) { Ab = A + (size_t)z * NN * NN; aStride = NN; }
    else                     { Ab = A;                        aStride = EE; }

    const float* Bb = Bm;
    int bStride = 0;
    if (MODE == MODE_S)      { Bb = Bm + (size_t)z * NN * DD;         bStride = DD; }
    else if (MODE == MODE_O) { Bb = Bm + (size_t)z * (size_t)D2 * NN; bStride = NN; }

    float acc[4][4][4];
#pragma unroll
    for (int i = 0; i < 4; i++)
#pragma unroll
        for (int j = 0; j < 4; j++)
#pragma unroll
            for (int q = 0; q < 4; q++) acc[i][j][q] = 0.0f;

    // ldmatrix per-lane base addresses
    const int ti = lane >> 3, rin = lane & 7;
    // A tiles: ti0:(r,k) ti1:(r+8,k) ti2:(r,k+8) ti3:(r+8,k+8)
    const int a_row = wm * 64 + ((ti & 1) << 3) + rin;
    const int a_kof = (ti >> 1) << 3;
    // B tiles: ti0:(n,k) ti1:(n,k+8) ti2:(n+8,k) ti3:(n+8,k+8)
    const int b_row = wn * 32 + ((ti >> 1) << 3) + rin;
    const int b_kof = (ti & 1) << 3;

    const uint32_t aHiAddr = smem_u32(aHi), aLoAddr = smem_u32(aLo);
    const uint32_t bHiAddr = smem_u32(bHi), bLoAddr = smem_u32(bLo);

    const int nchunk = Kd >> 6;
    for (int c = 0; c < nchunk; c++) {
        const int k0 = c << 6;
        // ---- A tile [128 m x 64 k], K contiguous
#pragma unroll
        for (int u = 0; u < 8; u++) {
            int unit = u * 256 + tid;
            int r = unit >> 4, g = unit & 15;
            float4 v = *(const float4*)&Ab[(size_t)(bm0 + r) * aStride + k0 + g * 4];
            split_store(aHi, aLo, r, g, v);
        }
        // ---- B tile [128 n x 64 k]
        if (MODE == MODE_S || MODE == MODE_O) {
#pragma unroll
            for (int u = 0; u < 8; u++) {
                int unit = u * 256 + tid;
                int r = unit >> 4, g = unit & 15;
                float4 v = *(const float4*)&Bb[(size_t)(bn0 + r) * bStride + k0 + g * 4];
                split_store(bHi, bLo, r, g, v);
            }
        } else {
            // weight matrix: B[n][k] = W[k][n]
#pragma unroll
            for (int u = 0; u < 8; u++) {
                int unit = u * 256 + tid;
                int g = unit >> 7, r = unit & 127;
                const float* p = &Bm[(size_t)(k0 + g * 4) * EE + bn0 + r];
                float4 v = make_float4(p[0], p[EE], p[2 * EE], p[3 * EE]);
                split_store(bHi, bLo, r, g, v);
            }
        }
        __syncthreads();

        // ---- compute: 4 k16 steps, 3 passes sharing accumulators
#pragma unroll
        for (int ks = 0; ks < 4; ks++) {
            const int kk = ks * 16;
            uint32_t Ah[4][4], Al[4][4], Bh[4][2], Bl[4][2];
#pragma unroll
            for (int mf = 0; mf < 4; mf++) {
                uint32_t off = ((a_row + mf * 16) * PITCH + kk + a_kof) * 2;
                LDMX4(Ah[mf][0], Ah[mf][1], Ah[mf][2], Ah[mf][3], aHiAddr + off);
                LDMX4(Al[mf][0], Al[mf][1], Al[mf][2], Al[mf][3], aLoAddr + off);
            }
#pragma unroll
            for (int p = 0; p < 2; p++) {
                uint32_t off = ((b_row + p * 16) * PITCH + kk + b_kof) * 2;
                uint32_t r0, r1, r2, r3;
                LDMX4(r0, r1, r2, r3, bHiAddr + off);
                Bh[2 * p][0] = r0; Bh[2 * p][1] = r1;
                Bh[2 * p + 1][0] = r2; Bh[2 * p + 1][1] = r3;
                LDMX4(r0, r1, r2, r3, bLoAddr + off);
                Bl[2 * p][0] = r0; Bl[2 * p][1] = r1;
                Bl[2 * p + 1][0] = r2; Bl[2 * p + 1][1] = r3;
            }
#pragma unroll
            for (int mf = 0; mf < 4; mf++)
#pragma unroll
                for (int nf = 0; nf < 4; nf++) {
                    MMA16816(acc[mf][nf], Ah[mf], Bh[nf]);
                    MMA16816(acc[mf][nf], Ah[mf], Bl[nf]);
                    MMA16816(acc[mf][nf], Al[mf], Bh[nf]);
                }
        }
        __syncthreads();
    }

    // ---- epilogue: fragment scatter ----------------------------------------
#pragma unroll
    for (int mf = 0; mf < 4; mf++) {
#pragma unroll
        for (int half = 0; half < 2; half++) {
            const int m = bm0 + wm * 64 + mf * 16 + tgrp + half * 8;
            const int b_ = m >> 11, n = m & 2047;
#pragma unroll
            for (int nf = 0; nf < 4; nf++) {
                const int ch = bn0 + wn * 32 + nf * 8 + tig * 2;
                float v0 = acc[mf][nf][half * 2 + 0];
                float v1 = acc[mf][nf][half * 2 + 1];
                if (MODE == MODE_Q) {
                    int h2 = ch >> 6, d0 = ch & 63;
                    float2 v = make_float2(v0 * 0.125f, v1 * 0.125f);
                    *(float2*)&g_q[((size_t)(b_ * H2 + h2) * NN + n) * DD + d0] = v;
                } else if (MODE == MODE_K) {
                    int h2 = ch >> 6, d0 = ch & 63;
                    *(float2*)&g_k[((size_t)(b_ * H2 + h2) * NN + n) * DD + d0] =
                        make_float2(v0, v1);
                } else if (MODE == MODE_V) {
                    int h = ch >> 7, c0 = ch & 127;
                    float* p = &g_vT[((size_t)(b_ * HH + h) * D2 + c0) * NN + n];
                    p[0] = v0;
                    p[NN] = v1;
                } else if (MODE == MODE_S) {
                    *(float2*)&g_s[(size_t)z * NN * NN + (size_t)m * NN + ch] =
                        make_float2(v0, v1);
                } else if (MODE == MODE_O) {
                    *(float2*)&g_po[(size_t)z * NN * D2 + (size_t)m * D2 + ch] =
                        make_float2(v0, v1);
                } else {
                    *(float2*)&C[(size_t)m * EE + ch] = make_float2(v0, v1);
                }
            }
        }
    }
}

// ---------------- lambda ------------------------------------------------------
__global__ void lam_kernel(const float* __restrict__ lq1, const float* __restrict__ lk1,
                           const float* __restrict__ lq2, const float* __restrict__ lk2)
{
    int t = threadIdx.x;            // 64 threads
    float p1 = lq1[t] * lk1[t];
    float p2 = lq2[t] * lk2[t];
    for (int o = 16; o > 0; o >>= 1) {
        p1 += __shfl_xor_sync(0xffffffffu, p1, o);
        p2 += __shfl_xor_sync(0xffffffffu, p2, o);
    }
    __shared__ float sh[4];
    if ((t & 31) == 0) { sh[(t >> 5) * 2] = p1; sh[(t >> 5) * 2 + 1] = p2; }
    __syncthreads();
    if (t == 0) {
        float S1 = sh[0] + sh[2];
        float S2 = sh[1] + sh[3];
        float lam_init = 0.8f - 0.6f * expf(-0.3f * 12.0f);
        g_lam = expf(S1) - expf(S2) + lam_init;
    }
}

// ---------------- softmax + differential combine -----------------------------
__global__ __launch_bounds__(256)
void softmax_combine_kernel()
{
    __shared__ float r1[NN];
    __shared__ float r2[NN];
    __shared__ float redm1[8], redm2[8], reds1[8], reds2[8];

    const int z = blockIdx.x;          // bh*2048 + i
    const int bh = z >> 11;
    const int i = z & 2047;
    const int b_ = bh >> 3;
    const int h = bh & 7;

    const size_t base1 = ((size_t)(b_ * H2 + 2 * h) * NN + i) * NN;
    const size_t base2 = ((size_t)(b_ * H2 + 2 * h + 1) * NN + i) * NN;

    const int tid = threadIdx.x;
    const int lane = tid & 31, wid = tid >> 5;

    float m1 = -INFINITY, m2 = -INFINITY;
    for (int j = tid; j < NN; j += 256) {
        float v1 = g_s[base1 + j];
        float v2 = g_s[base2 + j];
        r1[j] = v1; r2[j] = v2;
        m1 = fmaxf(m1, v1);
        m2 = fmaxf(m2, v2);
    }
    for (int o = 16; o > 0; o >>= 1) {
        m1 = fmaxf(m1, __shfl_xor_sync(0xffffffffu, m1, o));
        m2 = fmaxf(m2, __shfl_xor_sync(0xffffffffu, m2, o));
    }
    if (lane == 0) { redm1[wid] = m1; redm2[wid] = m2; }
    __syncthreads();
    float M1 = redm1[0], M2 = redm2[0];
#pragma unroll
    for (int w = 1; w < 8; w++) {
        M1 = fmaxf(M1, redm1[w]);
        M2 = fmaxf(M2, redm2[w]);
    }

    float s1 = 0.0f, s2 = 0.0f;
    for (int j = tid; j < NN; j += 256) {
        float e1 = expf(r1[j] - M1);
        float e2 = expf(r2[j] - M2);
        r1[j] = e1; r2[j] = e2;
        s1 += e1; s2 += e2;
    }
    for (int o = 16; o > 0; o >>= 1) {
        s1 += __shfl_xor_sync(0xffffffffu, s1, o);
        s2 += __shfl_xor_sync(0xffffffffu, s2, o);
    }
    if (lane == 0) { reds1[wid] = s1; reds2[wid] = s2; }
    __syncthreads();
    float S1 = 0.0f, S2 = 0.0f;
#pragma unroll
    for (int w = 0; w < 8; w++) { S1 += reds1[w]; S2 += reds2[w]; }

    const float inv1 = 1.0f / S1;
    const float linv2 = g_lam / S2;
    const size_t wbase = ((size_t)bh * NN + i) * NN;
    for (int j = tid; j < NN; j += 256) {
        g_w[wbase + j] = r1[j] * inv1 - r2[j] * linv2;
    }
}

// ---------------- per-head LayerNorm ------------------------------------------
__global__ __launch_bounds__(128)
void ln_kernel(const float* __restrict__ ln_g, const float* __restrict__ ln_b)
{
    __shared__ float sh1[4], sh2[4];
    const int z = blockIdx.x;          // bh*2048 + n
    const int bh = z >> 11;
    const int n = z & 2047;
    const int b_ = bh >> 3;
    const int h = bh & 7;
    const int tid = threadIdx.x;
    const int lane = tid & 31, wid = tid >> 5;

    float o = g_po[(size_t)z * D2 + tid];

    float s = o;
    for (int off = 16; off > 0; off >>= 1) s += __shfl_xor_sync(0xffffffffu, s, off);
    if (lane == 0) sh1[wid] = s;
    __syncthreads();
    float mu = (sh1[0] + sh1[1] + sh1[2] + sh1[3]) * (1.0f / 128.0f);

    float d = o - mu;
    float sq = d * d;
    for (int off = 16; off > 0; off >>= 1) sq += __shfl_xor_sync(0xffffffffu, sq, off);
    if (lane == 0) sh2[wid] = sq;
    __syncthreads();
    float var = (sh2[0] + sh2[1] + sh2[2] + sh2[3]) * (1.0f / 128.0f);

    float y = d * rsqrtf(var + 1e-5f) * ln_g[tid] + ln_b[tid];
    g_oln[((size_t)(b_ * NN + n)) * EE + h * D2 + tid] = y;
}

// ---------------- launch ------------------------------------------------------
extern "C" void kernel_launch(void* const* d_in, const int* in_sizes, int n_in,
                              void* d_out, int out_size)
{
    const float* x   = (const float*)d_in[0];
    const float* Wq  = (const float*)d_in[1];
    const float* Wk  = (const float*)d_in[2];
    const float* Wv  = (const float*)d_in[3];
    const float* Wo  = (const float*)d_in[4];
    const float* lq1 = (const float*)d_in[5];
    const float* lk1 = (const float*)d_in[6];
    const float* lq2 = (const float*)d_in[7];
    const float* lk2 = (const float*)d_in[8];
    const float* lng = (const float*)d_in[9];
    const float* lnb = (const float*)d_in[10];
    float* out = (float*)d_out;

    float *p_q, *p_k, *p_vT, *p_w, *p_oln;
    cudaGetSymbolAddress((void**)&p_q,   g_q);
    cudaGetSymbolAddress((void**)&p_k,   g_k);
    cudaGetSymbolAddress((void**)&p_vT,  g_vT);
    cudaGetSymbolAddress((void**)&p_w,   g_w);
    cudaGetSymbolAddress((void**)&p_oln, g_oln);

    cudaFuncSetAttribute(tgemm<MODE_Q>,     cudaFuncAttributeMaxDynamicSharedMemorySize, SMEM_DYN);
    cudaFuncSetAttribute(tgemm<MODE_K>,     cudaFuncAttributeMaxDynamicSharedMemorySize, SMEM_DYN);
    cudaFuncSetAttribute(tgemm<MODE_V>,     cudaFuncAttributeMaxDynamicSharedMemorySize, SMEM_DYN);
    cudaFuncSetAttribute(tgemm<MODE_S>,     cudaFuncAttributeMaxDynamicSharedMemorySize, SMEM_DYN);
    cudaFuncSetAttribute(tgemm<MODE_O>,     cudaFuncAttributeMaxDynamicSharedMemorySize, SMEM_DYN);
    cudaFuncSetAttribute(tgemm<MODE_FINAL>, cudaFuncAttributeMaxDynamicSharedMemorySize, SMEM_DYN);

    lam_kernel<<<1, 64>>>(lq1, lk1, lq2, lk2);

    // projections: [4096,1024] @ [1024,1024]
    tgemm<MODE_Q><<<dim3(8, 32, 1), 256, SMEM_DYN>>>(x, Wq, nullptr, EE);
    tgemm<MODE_K><<<dim3(8, 32, 1), 256, SMEM_DYN>>>(x, Wk, nullptr, EE);
    tgemm<MODE_V><<<dim3(8, 32, 1), 256, SMEM_DYN>>>(x, Wv, nullptr, EE);

    // scores: 32 half-heads, [2048,64] @ [2048,64]^T
    tgemm<MODE_S><<<dim3(16, 16, BB * H2), 256, SMEM_DYN>>>(p_q, p_k, nullptr, DD);

    softmax_combine_kernel<<<BB * HH * NN, 256>>>();

    // o = w @ v : 16 heads, [2048,2048] @ [128,2048]^T
    tgemm<MODE_O><<<dim3(1, 16, BB * HH), 256, SMEM_DYN>>>(p_w, p_vT, nullptr, NN);

    ln_kernel<<<BB * HH * NN, 128>>>(lng, lnb);

    // final: [4096,1024] @ [1024,1024] -> out
    tgemm<MODE_FINAL><<<dim3(8, 32, 1), 256, SMEM_DYN>>>(p_oln, Wo, out, EE);
}

// round 8
// speedup vs baseline: 2.3937x; 1.1026x over previous
#include <cuda_runtime.h>
#include <cuda_bf16.h>
#include <stdint.h>
#include <math.h>

// Problem constants
#define BB 2
#define NN 2048
#define EE 1024
#define HH 8
#define DD 64          // half-head dim
#define D2 128         // 2*D
#define H2 16          // 2*H
#define MROWS 4096     // B*N

// ---------------- scratch (device globals) -----------------------------------
// pre-split bf16 hi/lo operands
__device__ __nv_bfloat16 g_xh [(size_t)MROWS * EE];
__device__ __nv_bfloat16 g_xl [(size_t)MROWS * EE];
__device__ __nv_bfloat16 g_wqTh[(size_t)EE * EE], g_wqTl[(size_t)EE * EE];
__device__ __nv_bfloat16 g_wkTh[(size_t)EE * EE], g_wkTl[(size_t)EE * EE];
__device__ __nv_bfloat16 g_wvTh[(size_t)EE * EE], g_wvTl[(size_t)EE * EE];
__device__ __nv_bfloat16 g_woTh[(size_t)EE * EE], g_woTl[(size_t)EE * EE];
__device__ __nv_bfloat16 g_qh [(size_t)BB * H2 * NN * DD], g_ql [(size_t)BB * H2 * NN * DD];
__device__ __nv_bfloat16 g_kh [(size_t)BB * H2 * NN * DD], g_kl [(size_t)BB * H2 * NN * DD];
__device__ __nv_bfloat16 g_vTh[(size_t)BB * HH * D2 * NN], g_vTl[(size_t)BB * HH * D2 * NN];
__device__ __nv_bfloat16 g_wh [(size_t)BB * HH * NN * NN], g_wl [(size_t)BB * HH * NN * NN];
__device__ __nv_bfloat16 g_olnh[(size_t)MROWS * EE], g_olnl[(size_t)MROWS * EE];
__device__ float g_s  [(size_t)BB * H2 * NN * NN];   // raw scores fp32
__device__ float g_po [(size_t)BB * HH * NN * D2];   // pre-LN o fp32
__device__ float g_lam;

// ---------------- helpers -----------------------------------------------------
__device__ __forceinline__ uint32_t smem_u32(const void* p) {
    return (uint32_t)__cvta_generic_to_shared(p);
}

#define LDMX4(r0, r1, r2, r3, addr)                                            \
    asm volatile("ldmatrix.sync.aligned.m8n8.x4.shared.b16 {%0,%1,%2,%3}, [%4];" \
                 : "=r"(r0), "=r"(r1), "=r"(r2), "=r"(r3) : "r"(addr))

#define MMA16816(c, a, b)                                                      \
    asm volatile(                                                              \
        "mma.sync.aligned.m16n8k16.row.col.f32.bf16.bf16.f32 "                 \
        "{%0,%1,%2,%3}, {%4,%5,%6,%7}, {%8,%9}, {%0,%1,%2,%3};"                \
        : "+f"((c)[0]), "+f"((c)[1]), "+f"((c)[2]), "+f"((c)[3])               \
        : "r"((a)[0]), "r"((a)[1]), "r"((a)[2]), "r"((a)[3]),                  \
          "r"((b)[0]), "r"((b)[1]))

#define CP16(dst, src)                                                         \
    asm volatile("cp.async.cg.shared.global [%0], [%1], 16;"                   \
                 :: "r"(dst), "l"(src) : "memory")
#define CP_COMMIT asm volatile("cp.async.commit_group;" ::: "memory")
#define CP_WAIT0  asm volatile("cp.async.wait_group 0;" ::: "memory")
#define CP_WAIT1  asm volatile("cp.async.wait_group 1;" ::: "memory")

__device__ __forceinline__ __nv_bfloat16 bfh(float v) { return __float2bfloat16_rn(v); }
__device__ __forceinline__ float bff(__nv_bfloat16 v) { return __bfloat162float(v); }

// ---------------- bf16x3 mma.sync GEMM, cp.async double-buffered --------------
#define MODE_Q     0
#define MODE_K     1
#define MODE_V     2
#define MODE_S     3
#define MODE_O     4
#define MODE_FINAL 5

#define PITCH 72                       // bf16 elems per smem row (144B)
#define TILE_BYTES (128 * PITCH * 2)   // 18432
#define STAGE_BYTES (4 * TILE_BYTES)   // 73728
static constexpr int SMEM_DYN = 2 * STAGE_BYTES;   // 147456

// prefetch one K-chunk (64) of all 4 tiles into a stage
__device__ __forceinline__ void do_prefetch(
    uint32_t sbase, int tid, int k0,
    const __nv_bfloat16* Ahb, const __nv_bfloat16* Alb,
    const __nv_bfloat16* Bhb, const __nv_bfloat16* Blb,
    int Kd, int bm0, int bn0)
{
#pragma unroll
    for (int u = 0; u < 4; u++) {
        int w = u * 256 + tid;
        int row = w >> 3, c8 = w & 7;
        uint32_t doff = (uint32_t)(row * 144 + c8 * 16);
        size_t aoff = (size_t)(bm0 + row) * Kd + k0 + c8 * 8;
        size_t boff = (size_t)(bn0 + row) * Kd + k0 + c8 * 8;
        CP16(sbase + doff,                  Ahb + aoff);
        CP16(sbase + TILE_BYTES + doff,     Alb + aoff);
        CP16(sbase + 2 * TILE_BYTES + doff, Bhb + boff);
        CP16(sbase + 3 * TILE_BYTES + doff, Blb + boff);
    }
}

template <int MODE>
__global__ __launch_bounds__(256)
void tgemm(const __nv_bfloat16* __restrict__ Ah_, const __nv_bfloat16* __restrict__ Al_,
           const __nv_bfloat16* __restrict__ Bh_, const __nv_bfloat16* __restrict__ Bl_,
           float* __restrict__ C, int Kd, long aBatch, long bBatch)
{
    extern __shared__ char dsm[];
    const uint32_t sbase0 = smem_u32(dsm);

    const int tid  = threadIdx.x;
    const int z    = blockIdx.z;
    const int bm0  = blockIdx.y * 128;
    const int bn0  = blockIdx.x * 128;
    const int wid  = tid >> 5, lane = tid & 31;
    const int wm   = wid >> 2, wn = wid & 3;   // warp tile: rows wm*64, cols wn*32
    const int tgrp = lane >> 2, tig = lane & 3;

    const __nv_bfloat16* Ahb = Ah_ + (size_t)z * aBatch;
    const __nv_bfloat16* Alb = Al_ + (size_t)z * aBatch;
    const __nv_bfloat16* Bhb = Bh_ + (size_t)z * bBatch;
    const __nv_bfloat16* Blb = Bl_ + (size_t)z * bBatch;

    float acc[4][4][4];
#pragma unroll
    for (int i = 0; i < 4; i++)
#pragma unroll
        for (int j = 0; j < 4; j++)
#pragma unroll
            for (int q = 0; q < 4; q++) acc[i][j][q] = 0.0f;

    // ldmatrix per-lane addressing
    const int ti = lane >> 3, rin = lane & 7;
    const int a_row = wm * 64 + ((ti & 1) << 3) + rin;
    const int a_kof = (ti >> 1) << 3;
    const int b_row = wn * 32 + ((ti >> 1) << 3) + rin;
    const int b_kof = (ti & 1) << 3;

    const int nchunk = Kd >> 6;

    do_prefetch(sbase0, tid, 0, Ahb, Alb, Bhb, Blb, Kd, bm0, bn0);
    CP_COMMIT;

    for (int c = 0; c < nchunk; c++) {
        if (c + 1 < nchunk) {
            do_prefetch(sbase0 + ((c + 1) & 1) * STAGE_BYTES, tid, (c + 1) << 6,
                        Ahb, Alb, Bhb, Blb, Kd, bm0, bn0);
            CP_COMMIT;
            CP_WAIT1;
        } else {
            CP_WAIT0;
        }
        __syncthreads();

        const uint32_t aHiAddr = sbase0 + (c & 1) * STAGE_BYTES;
        const uint32_t aLoAddr = aHiAddr + TILE_BYTES;
        const uint32_t bHiAddr = aHiAddr + 2 * TILE_BYTES;
        const uint32_t bLoAddr = aHiAddr + 3 * TILE_BYTES;

#pragma unroll
        for (int ks = 0; ks < 4; ks++) {
            const int kk = ks * 16;
            uint32_t Ahf[4][4], Alf[4][4], Bhf[4][2], Blf[4][2];
#pragma unroll
            for (int mf = 0; mf < 4; mf++) {
                uint32_t off = (uint32_t)(((a_row + mf * 16) * PITCH + kk + a_kof) * 2);
                LDMX4(Ahf[mf][0], Ahf[mf][1], Ahf[mf][2], Ahf[mf][3], aHiAddr + off);
                LDMX4(Alf[mf][0], Alf[mf][1], Alf[mf][2], Alf[mf][3], aLoAddr + off);
            }
#pragma unroll
            for (int p = 0; p < 2; p++) {
                uint32_t off = (uint32_t)(((b_row + p * 16) * PITCH + kk + b_kof) * 2);
                uint32_t r0, r1, r2, r3;
                LDMX4(r0, r1, r2, r3, bHiAddr + off);
                Bhf[2 * p][0] = r0; Bhf[2 * p][1] = r1;
                Bhf[2 * p + 1][0] = r2; Bhf[2 * p + 1][1] = r3;
                LDMX4(r0, r1, r2, r3, bLoAddr + off);
                Blf[2 * p][0] = r0; Blf[2 * p][1] = r1;
                Blf[2 * p + 1][0] = r2; Blf[2 * p + 1][1] = r3;
            }
#pragma unroll
            for (int mf = 0; mf < 4; mf++)
#pragma unroll
                for (int nf = 0; nf < 4; nf++) {
                    MMA16816(acc[mf][nf], Ahf[mf], Bhf[nf]);
                    MMA16816(acc[mf][nf], Ahf[mf], Blf[nf]);
                    MMA16816(acc[mf][nf], Alf[mf], Bhf[nf]);
                }
        }
        __syncthreads();
    }

    // ---- epilogue: fragment scatter ----------------------------------------
#pragma unroll
    for (int mf = 0; mf < 4; mf++) {
#pragma unroll
        for (int half = 0; half < 2; half++) {
            const int m = bm0 + wm * 64 + mf * 16 + tgrp + half * 8;
            const int b_ = m >> 11, n = m & 2047;
#pragma unroll
            for (int nf = 0; nf < 4; nf++) {
                const int ch = bn0 + wn * 32 + nf * 8 + tig * 2;
                float v0 = acc[mf][nf][half * 2 + 0];
                float v1 = acc[mf][nf][half * 2 + 1];
                if (MODE == MODE_Q || MODE == MODE_K) {
                    if (MODE == MODE_Q) { v0 *= 0.125f; v1 *= 0.125f; }
                    int h2i = ch >> 6, d0 = ch & 63;
                    size_t idx = ((size_t)(b_ * H2 + h2i) * NN + n) * DD + d0;
                    __nv_bfloat162 h, l;
                    h.x = bfh(v0); h.y = bfh(v1);
                    l.x = bfh(v0 - bff(h.x)); l.y = bfh(v1 - bff(h.y));
                    if (MODE == MODE_Q) {
                        *(__nv_bfloat162*)&g_qh[idx] = h;
                        *(__nv_bfloat162*)&g_ql[idx] = l;
                    } else {
                        *(__nv_bfloat162*)&g_kh[idx] = h;
                        *(__nv_bfloat162*)&g_kl[idx] = l;
                    }
                } else if (MODE == MODE_V) {
                    int h = ch >> 7, c0 = ch & 127;
                    size_t idx = ((size_t)(b_ * HH + h) * D2 + c0) * NN + n;
                    __nv_bfloat16 h0 = bfh(v0), h1 = bfh(v1);
                    g_vTh[idx] = h0;       g_vTh[idx + NN] = h1;
                    g_vTl[idx] = bfh(v0 - bff(h0));
                    g_vTl[idx + NN] = bfh(v1 - bff(h1));
                } else if (MODE == MODE_S) {
                    *(float2*)&g_s[(size_t)z * NN * NN + (size_t)m * NN + ch] =
                        make_float2(v0, v1);
                } else if (MODE == MODE_O) {
                    *(float2*)&g_po[(size_t)z * NN * D2 + (size_t)m * D2 + ch] =
                        make_float2(v0, v1);
                } else {
                    *(float2*)&C[(size_t)m * EE + ch] = make_float2(v0, v1);
                }
            }
        }
    }
}

// ---------------- operand pre-split kernels -----------------------------------
__global__ __launch_bounds__(256)
void split_x_kernel(const float* __restrict__ x)
{
    int i = blockIdx.x * 256 + threadIdx.x;      // float4 index
    float4 v = ((const float4*)x)[i];
    __nv_bfloat162 h0, h1, l0, l1;
    h0.x = bfh(v.x); h0.y = bfh(v.y); h1.x = bfh(v.z); h1.y = bfh(v.w);
    l0.x = bfh(v.x - bff(h0.x)); l0.y = bfh(v.y - bff(h0.y));
    l1.x = bfh(v.z - bff(h1.x)); l1.y = bfh(v.w - bff(h1.y));
    ((__nv_bfloat162*)g_xh)[2 * i] = h0;
    ((__nv_bfloat162*)g_xh)[2 * i + 1] = h1;
    ((__nv_bfloat162*)g_xl)[2 * i] = l0;
    ((__nv_bfloat162*)g_xl)[2 * i + 1] = l1;
}

__global__ __launch_bounds__(256)
void split_wT_kernel(const float* __restrict__ W,
                     __nv_bfloat16* __restrict__ Th, __nv_bfloat16* __restrict__ Tl)
{
    __shared__ float tile[32][33];
    const int bx = blockIdx.x * 32;   // n block
    const int by = blockIdx.y * 32;   // k block
    const int tx = threadIdx.x & 31, ty = threadIdx.x >> 5;   // 32x8
#pragma unroll
    for (int r = 0; r < 32; r += 8)
        tile[ty + r][tx] = W[(size_t)(by + ty + r) * EE + bx + tx];
    __syncthreads();
#pragma unroll
    for (int r = 0; r < 32; r += 8) {
        float v = tile[tx][ty + r];   // = W[by+tx][bx+ty+r]
        __nv_bfloat16 h = bfh(v);
        size_t idx = (size_t)(bx + ty + r) * EE + by + tx;
        Th[idx] = h;
        Tl[idx] = bfh(v - bff(h));
    }
}

// ---------------- lambda ------------------------------------------------------
__global__ void lam_kernel(const float* __restrict__ lq1, const float* __restrict__ lk1,
                           const float* __restrict__ lq2, const float* __restrict__ lk2)
{
    int t = threadIdx.x;            // 64 threads
    float p1 = lq1[t] * lk1[t];
    float p2 = lq2[t] * lk2[t];
    for (int o = 16; o > 0; o >>= 1) {
        p1 += __shfl_xor_sync(0xffffffffu, p1, o);
        p2 += __shfl_xor_sync(0xffffffffu, p2, o);
    }
    __shared__ float sh[4];
    if ((t & 31) == 0) { sh[(t >> 5) * 2] = p1; sh[(t >> 5) * 2 + 1] = p2; }
    __syncthreads();
    if (t == 0) {
        float S1 = sh[0] + sh[2];
        float S2 = sh[1] + sh[3];
        float lam_init = 0.8f - 0.6f * expf(-0.3f * 12.0f);
        g_lam = expf(S1) - expf(S2) + lam_init;
    }
}

// ---------------- softmax + differential combine -----------------------------
__global__ __launch_bounds__(256)
void softmax_combine_kernel()
{
    __shared__ float r1[NN];
    __shared__ float r2[NN];
    __shared__ float redm1[8], redm2[8], reds1[8], reds2[8];

    const int z = blockIdx.x;          // bh*2048 + i
    const int bh = z >> 11;
    const int i = z & 2047;
    const int b_ = bh >> 3;
    const int h = bh & 7;

    const size_t base1 = ((size_t)(b_ * H2 + 2 * h) * NN + i) * NN;
    const size_t base2 = ((size_t)(b_ * H2 + 2 * h + 1) * NN + i) * NN;

    const int tid = threadIdx.x;
    const int lane = tid & 31, wid = tid >> 5;

    float m1 = -INFINITY, m2 = -INFINITY;
    for (int j = tid; j < NN; j += 256) {
        float v1 = g_s[base1 + j];
        float v2 = g_s[base2 + j];
        r1[j] = v1; r2[j] = v2;
        m1 = fmaxf(m1, v1);
        m2 = fmaxf(m2, v2);
    }
    for (int o = 16; o > 0; o >>= 1) {
        m1 = fmaxf(m1, __shfl_xor_sync(0xffffffffu, m1, o));
        m2 = fmaxf(m2, __shfl_xor_sync(0xffffffffu, m2, o));
    }
    if (lane == 0) { redm1[wid] = m1; redm2[wid] = m2; }
    __syncthreads();
    float M1 = redm1[0], M2 = redm2[0];
#pragma unroll
    for (int w = 1; w < 8; w++) {
        M1 = fmaxf(M1, redm1[w]);
        M2 = fmaxf(M2, redm2[w]);
    }

    float s1 = 0.0f, s2 = 0.0f;
    for (int j = tid; j < NN; j += 256) {
        float e1 = expf(r1[j] - M1);
        float e2 = expf(r2[j] - M2);
        r1[j] = e1; r2[j] = e2;
        s1 += e1; s2 += e2;
    }
    for (int o = 16; o > 0; o >>= 1) {
        s1 += __shfl_xor_sync(0xffffffffu, s1, o);
        s2 += __shfl_xor_sync(0xffffffffu, s2, o);
    }
    if (lane == 0) { reds1[wid] = s1; reds2[wid] = s2; }
    __syncthreads();
    float S1 = 0.0f, S2 = 0.0f;
#pragma unroll
    for (int w = 0; w < 8; w++) { S1 += reds1[w]; S2 += reds2[w]; }

    const float inv1 = 1.0f / S1;
    const float linv2 = g_lam / S2;
    const size_t wbase = ((size_t)bh * NN + i) * NN;
    for (int j = tid; j < NN; j += 256) {
        float wv = r1[j] * inv1 - r2[j] * linv2;
        __nv_bfloat16 hw = bfh(wv);
        g_wh[wbase + j] = hw;
        g_wl[wbase + j] = bfh(wv - bff(hw));
    }
}

// ---------------- per-head LayerNorm ------------------------------------------
__global__ __launch_bounds__(128)
void ln_kernel(const float* __restrict__ ln_g, const float* __restrict__ ln_b)
{
    __shared__ float sh1[4], sh2[4];
    const int z = blockIdx.x;          // bh*2048 + n
    const int bh = z >> 11;
    const int n = z & 2047;
    const int b_ = bh >> 3;
    const int h = bh & 7;
    const int tid = threadIdx.x;
    const int lane = tid & 31, wid = tid >> 5;

    float o = g_po[(size_t)z * D2 + tid];

    float s = o;
    for (int off = 16; off > 0; off >>= 1) s += __shfl_xor_sync(0xffffffffu, s, off);
    if (lane == 0) sh1[wid] = s;
    __syncthreads();
    float mu = (sh1[0] + sh1[1] + sh1[2] + sh1[3]) * (1.0f / 128.0f);

    float d = o - mu;
    float sq = d * d;
    for (int off = 16; off > 0; off >>= 1) sq += __shfl_xor_sync(0xffffffffu, sq, off);
    if (lane == 0) sh2[wid] = sq;
    __syncthreads();
    float var = (sh2[0] + sh2[1] + sh2[2] + sh2[3]) * (1.0f / 128.0f);

    float y = d * rsqrtf(var + 1e-5f) * ln_g[tid] + ln_b[tid];
    size_t idx = ((size_t)(b_ * NN + n)) * EE + h * D2 + tid;
    __nv_bfloat16 hy = bfh(y);
    g_olnh[idx] = hy;
    g_olnl[idx] = bfh(y - bff(hy));
}

// ---------------- launch ------------------------------------------------------
extern "C" void kernel_launch(void* const* d_in, const int* in_sizes, int n_in,
                              void* d_out, int out_size)
{
    const float* x   = (const float*)d_in[0];
    const float* Wq  = (const float*)d_in[1];
    const float* Wk  = (const float*)d_in[2];
    const float* Wv  = (const float*)d_in[3];
    const float* Wo  = (const float*)d_in[4];
    const float* lq1 = (const float*)d_in[5];
    const float* lk1 = (const float*)d_in[6];
    const float* lq2 = (const float*)d_in[7];
    const float* lk2 = (const float*)d_in[8];
    const float* lng = (const float*)d_in[9];
    const float* lnb = (const float*)d_in[10];
    float* out = (float*)d_out;

    // resolve device-global addresses
    __nv_bfloat16 *p_xh, *p_xl, *p_wqTh, *p_wqTl, *p_wkTh, *p_wkTl;
    __nv_bfloat16 *p_wvTh, *p_wvTl, *p_woTh, *p_woTl;
    __nv_bfloat16 *p_qh, *p_ql, *p_kh, *p_kl, *p_vTh, *p_vTl;
    __nv_bfloat16 *p_wh, *p_wl, *p_olnh, *p_olnl;
    cudaGetSymbolAddress((void**)&p_xh, g_xh);     cudaGetSymbolAddress((void**)&p_xl, g_xl);
    cudaGetSymbolAddress((void**)&p_wqTh, g_wqTh); cudaGetSymbolAddress((void**)&p_wqTl, g_wqTl);
    cudaGetSymbolAddress((void**)&p_wkTh, g_wkTh); cudaGetSymbolAddress((void**)&p_wkTl, g_wkTl);
    cudaGetSymbolAddress((void**)&p_wvTh, g_wvTh); cudaGetSymbolAddress((void**)&p_wvTl, g_wvTl);
    cudaGetSymbolAddress((void**)&p_woTh, g_woTh); cudaGetSymbolAddress((void**)&p_woTl, g_woTl);
    cudaGetSymbolAddress((void**)&p_qh, g_qh);     cudaGetSymbolAddress((void**)&p_ql, g_ql);
    cudaGetSymbolAddress((void**)&p_kh, g_kh);     cudaGetSymbolAddress((void**)&p_kl, g_kl);
    cudaGetSymbolAddress((void**)&p_vTh, g_vTh);   cudaGetSymbolAddress((void**)&p_vTl, g_vTl);
    cudaGetSymbolAddress((void**)&p_wh, g_wh);     cudaGetSymbolAddress((void**)&p_wl, g_wl);
    cudaGetSymbolAddress((void**)&p_olnh, g_olnh); cudaGetSymbolAddress((void**)&p_olnl, g_olnl);

    cudaFuncSetAttribute(tgemm<MODE_Q>,     cudaFuncAttributeMaxDynamicSharedMemorySize, SMEM_DYN);
    cudaFuncSetAttribute(tgemm<MODE_K>,     cudaFuncAttributeMaxDynamicSharedMemorySize, SMEM_DYN);
    cudaFuncSetAttribute(tgemm<MODE_V>,     cudaFuncAttributeMaxDynamicSharedMemorySize, SMEM_DYN);
    cudaFuncSetAttribute(tgemm<MODE_S>,     cudaFuncAttributeMaxDynamicSharedMemorySize, SMEM_DYN);
    cudaFuncSetAttribute(tgemm<MODE_O>,     cudaFuncAttributeMaxDynamicSharedMemorySize, SMEM_DYN);
    cudaFuncSetAttribute(tgemm<MODE_FINAL>, cudaFuncAttributeMaxDynamicSharedMemorySize, SMEM_DYN);

    lam_kernel<<<1, 64>>>(lq1, lk1, lq2, lk2);

    // pre-split operands
    split_x_kernel<<<MROWS * EE / 4 / 256, 256>>>(x);
    dim3 tgrid(EE / 32, EE / 32);
    split_wT_kernel<<<tgrid, 256>>>(Wq, p_wqTh, p_wqTl);
    split_wT_kernel<<<tgrid, 256>>>(Wk, p_wkTh, p_wkTl);
    split_wT_kernel<<<tgrid, 256>>>(Wv, p_wvTh, p_wvTl);
    split_wT_kernel<<<tgrid, 256>>>(Wo, p_woTh, p_woTl);

    // projections: [4096,1024] @ [1024,1024]^T(K-major)
    tgemm<MODE_Q><<<dim3(8, 32, 1), 256, SMEM_DYN>>>(p_xh, p_xl, p_wqTh, p_wqTl, nullptr, EE, 0, 0);
    tgemm<MODE_K><<<dim3(8, 32, 1), 256, SMEM_DYN>>>(p_xh, p_xl, p_wkTh, p_wkTl, nullptr, EE, 0, 0);
    tgemm<MODE_V><<<dim3(8, 32, 1), 256, SMEM_DYN>>>(p_xh, p_xl, p_wvTh, p_wvTl, nullptr, EE, 0, 0);

    // scores: 32 half-heads, [2048,64] @ [2048,64]^T
    tgemm<MODE_S><<<dim3(16, 16, BB * H2), 256, SMEM_DYN>>>(
        p_qh, p_ql, p_kh, p_kl, nullptr, DD, (long)NN * DD, (long)NN * DD);

    softmax_combine_kernel<<<BB * HH * NN, 256>>>();

    // o = w @ v : 16 heads, [2048,2048] @ [128,2048]^T
    tgemm<MODE_O><<<dim3(1, 16, BB * HH), 256, SMEM_DYN>>>(
        p_wh, p_wl, p_vTh, p_vTl, nullptr, NN, (long)NN * NN, (long)D2 * NN);

    ln_kernel<<<BB * HH * NN, 128>>>(lng, lnb);

    // final: [4096,1024] @ [1024,1024]^T(K-major) -> out
    tgemm<MODE_FINAL><<<dim3(8, 32, 1), 256, SMEM_DYN>>>(
        p_olnh, p_olnl, p_woTh, p_woTl, out, EE, 0, 0);
}